// round 15
// baseline (speedup 1.0000x reference)
#include <cuda_runtime.h>
#include <cuda_fp16.h>
#include <mma.h>
#include <cstdint>
using namespace nvcuda;

#define N_NODES 100000
#define N_EDGES 1600000
#define NPAD    100352   // multiple of 256

__device__ int   g_cnt[N_NODES];     // zero at module load; re-zeroed in scan_write each run
__device__ int   g_fill[N_NODES];
__device__ float g_dis[N_NODES];
__device__ int   g_rowptr[N_NODES + 1];
__device__ int   g_bsum[256];
__device__ int   g_colsrc[N_EDGES];
__device__ __align__(16) __half g_xh [(size_t)NPAD * 32];   // dis*x (pre-scaled)
__device__ __align__(16) __half g_h16[(size_t)NPAD * 128];  // dis*h1 (pre-scaled)
__device__ __align__(16) __half g_hA [(size_t)NPAD * 128];  // h2
__device__ __align__(16) __half g_s3h[(size_t)NPAD * 32];   // dis*(h2@W3) (pre-scaled)

// Per-block edge-dtype detection: sample high words of the first 64 int64 slots.
#define DETECT_IS64(w32, is64_var)                                   \
    __shared__ int s_any;                                            \
    if (threadIdx.x == 0) s_any = 0;                                 \
    __syncthreads();                                                 \
    if (threadIdx.x < 64 && (w32)[2 * threadIdx.x + 1] != 0)         \
        atomicOr(&s_any, 1);                                         \
    __syncthreads();                                                 \
    const bool is64_var = (s_any == 0);

__device__ __forceinline__ int edge_at(const void* ed, bool is64, size_t idx) {
    return is64 ? (int)((const long long*)ed)[idx] : ((const int*)ed)[idx];
}

// ---- count in-degrees (2 edges per thread) ----
__global__ void prep_count(const void* __restrict__ ed, int N, int E) {
    DETECT_IS64((const int*)ed, is64);
    int i = blockIdx.x * blockDim.x + threadIdx.x;
    int halfE = E >> 1;
    if (i < halfE) {
        int d0, d1;
        if (is64) {
            longlong2 v = ((const longlong2*)ed)[(size_t)halfE + i];
            d0 = (int)v.x; d1 = (int)v.y;
        } else {
            int2 v = ((const int2*)ed)[(size_t)halfE + i];
            d0 = v.x; d1 = v.y;
        }
        if ((unsigned)d0 < (unsigned)N) atomicAdd(&g_cnt[d0], 1);
        if ((unsigned)d1 < (unsigned)N) atomicAdd(&g_cnt[d1], 1);
    }
    if ((E & 1) && i == halfE) {
        int d = edge_at(ed, is64, (size_t)E + (E - 1));
        if ((unsigned)d < (unsigned)N) atomicAdd(&g_cnt[d], 1);
    }
}

// ---- scan pass 1: per-block sums (warp shuffles) + dis/fill init ----
__global__ __launch_bounds__(1024) void scan_reduce(int N) {
    __shared__ int ws[32];
    int idx = blockIdx.x * 1024 + threadIdx.x;
    int c = (idx < N) ? g_cnt[idx] : 0;
    if (idx < N) { g_dis[idx] = rsqrtf((float)(c + 1)); g_fill[idx] = 0; }
    int v = c;
#pragma unroll
    for (int o = 16; o; o >>= 1) v += __shfl_down_sync(0xffffffffu, v, o);
    if ((threadIdx.x & 31) == 0) ws[threadIdx.x >> 5] = v;
    __syncthreads();
    if (threadIdx.x < 32) {
        int t = ws[threadIdx.x];
#pragma unroll
        for (int o = 16; o; o >>= 1) t += __shfl_down_sync(0xffffffffu, t, o);
        if (threadIdx.x == 0) g_bsum[blockIdx.x] = t;
    }
}

// ---- scan pass 2: shuffle scans, exclusive rowptr; re-zero cnt ----
__global__ __launch_bounds__(1024) void scan_write(int N, int nb) {
    __shared__ int ws[32];
    __shared__ int tops;
    const int tid = threadIdx.x;
    const int lane = tid & 31;
    const int idx = blockIdx.x * 1024 + tid;
    int v = (idx < N) ? g_cnt[idx] : 0;
    // warp-inclusive scan
    int inc = v;
#pragma unroll
    for (int o = 1; o < 32; o <<= 1) {
        int t = __shfl_up_sync(0xffffffffu, inc, o);
        if (lane >= o) inc += t;
    }
    if (lane == 31) ws[tid >> 5] = inc;
    __syncthreads();
    if (tid < 32) {                     // warp 0: exclusive scan of 32 warp totals
        int t = ws[tid];
        int ti = t;
#pragma unroll
        for (int o = 1; o < 32; o <<= 1) {
            int u = __shfl_up_sync(0xffffffffu, ti, o);
            if (tid >= o) ti += u;
        }
        ws[tid] = ti - t;
    } else if (tid < 64) {              // warp 1: top-level scan of nb (<=128) block sums
        int l = tid - 32;
        int b[4];
#pragma unroll
        for (int k = 0; k < 4; k++) { int j = l * 4 + k; b[k] = (j < nb) ? g_bsum[j] : 0; }
        int tot = b[0] + b[1] + b[2] + b[3];
        int ti = tot;
#pragma unroll
        for (int o = 1; o < 32; o <<= 1) {
            int u = __shfl_up_sync(0xffffffffu, ti, o);
            if (l >= o) ti += u;
        }
        int ex = ti - tot;              // exclusive before this lane's group of 4
#pragma unroll
        for (int k = 0; k < 4; k++) {
            int j = l * 4 + k;
            if (j == (int)blockIdx.x) tops = ex;
            ex += b[k];
        }
        if (blockIdx.x == (unsigned)(nb - 1)) {
            int total = __shfl_sync(0xffffffffu, ti, 31);
            if (l == 0) g_rowptr[N] = total;
        }
    }
    __syncthreads();
    if (idx < N) {
        g_rowptr[idx] = tops + ws[tid >> 5] + (inc - v);   // global exclusive
        g_cnt[idx] = 0;                                    // ready for next replay
    }
}

// ---- fill CSR + fused scaled x->fp16 convert (dis ready after scan_write) ----
__global__ void fill_csr(const void* __restrict__ ed, const float* __restrict__ x,
                         int E, int N) {
    DETECT_IS64((const int*)ed, is64);
    int i = blockIdx.x * blockDim.x + threadIdx.x;
    if (i < N * 8) {                      // 4 floats per thread, scaled by dis[row]
        float4 f = ((const float4*)x)[i];
        float d = g_dis[i >> 3];
        __half2 a = __floats2half2_rn(d * f.x, d * f.y);
        __half2 b = __floats2half2_rn(d * f.z, d * f.w);
        ((uint2*)g_xh)[i] = make_uint2(*(unsigned*)&a, *(unsigned*)&b);
    }
    if (i < E) {
        int s = edge_at(ed, is64, i);
        int d = edge_at(ed, is64, (size_t)E + i);
        if ((unsigned)s < (unsigned)N && (unsigned)d < (unsigned)N) {
            int pos = g_rowptr[d] + atomicAdd(&g_fill[d], 1);
            g_colsrc[pos] = s;
        }
    }
}

__device__ __forceinline__ float4 h4_to_f4(uint2 v) {
    __half2 a = *(__half2*)&v.x, b = *(__half2*)&v.y;
    float2 fa = __half22float2(a), fb = __half22float2(b);
    return make_float4(fa.x, fa.y, fb.x, fb.y);
}

// ---------------- FUSED agg + tensor-core GEMM (NOUT=128) ----------------
// As tile = Agg of this block's 128 rows, aggregated in-kernel from pre-scaled G.
// Y[r] = epi( di*(sum G[s] + G[r]) @ W ) [* dis if SCALE]
template <int K, bool SCALE>
__global__ __launch_bounds__(256) void fused_agg_wgemm(
    const __half* __restrict__ G, const float* __restrict__ Wf,
    const float* __restrict__ Bias, __half* __restrict__ Y, int N)
{
    constexpr int NOUT = 128;
    constexpr int WM = 4, MFRAG = 2, NFRAG = 4;
    constexpr int MBLK = 128;
    constexpr int LDA = K + 8, LDB = NOUT + 8;
    extern __shared__ __half smh[];
    __half* As = smh;
    __half* Bs = smh + MBLK * LDA;
    const int tid = threadIdx.x, wid = tid >> 5, lane = tid & 31;
    const int row0 = blockIdx.x * MBLK;

    for (int i = tid; i < K * NOUT; i += 256)
        Bs[(i / NOUT) * LDB + (i % NOUT)] = __float2half(Wf[i]);

    // aggregation: warp wid handles rows wid*16 .. wid*16+15
    for (int rr = 0; rr < 16; rr++) {
        const int r = wid * 16 + rr;
        const int node = row0 + r;
        if (node < N) {
            const float di = g_dis[node];
            const int beg = g_rowptr[node], end = g_rowptr[node + 1];
            if constexpr (K == 32) {
                float acc = __half2float(G[(size_t)node * 32 + lane]);
                int e = beg;
                for (; e + 8 <= end; e += 8) {
                    int s[8];
#pragma unroll
                    for (int j = 0; j < 8; j++) s[j] = g_colsrc[e + j];
                    float v[8];
#pragma unroll
                    for (int j = 0; j < 8; j++) v[j] = __half2float(G[(size_t)s[j] * 32 + lane]);
#pragma unroll
                    for (int j = 0; j < 8; j++) acc += v[j];
                }
                for (; e < end; e++) acc += __half2float(G[(size_t)g_colsrc[e] * 32 + lane]);
                As[r * LDA + lane] = __float2half(di * acc);
            } else {
                float4 acc = h4_to_f4(((const uint2*)(G + (size_t)node * 128))[lane]);
                int e = beg;
                for (; e + 8 <= end; e += 8) {
                    int s[8];
#pragma unroll
                    for (int j = 0; j < 8; j++) s[j] = g_colsrc[e + j];
                    uint2 raw[8];
#pragma unroll
                    for (int j = 0; j < 8; j++) raw[j] = ((const uint2*)(G + (size_t)s[j] * 128))[lane];
#pragma unroll
                    for (int j = 0; j < 8; j++) {
                        float4 v = h4_to_f4(raw[j]);
                        acc.x += v.x; acc.y += v.y; acc.z += v.z; acc.w += v.w;
                    }
                }
                for (; e < end; e++) {
                    float4 v = h4_to_f4(((const uint2*)(G + (size_t)g_colsrc[e] * 128))[lane]);
                    acc.x += v.x; acc.y += v.y; acc.z += v.z; acc.w += v.w;
                }
                __half2 a = __floats2half2_rn(di * acc.x, di * acc.y);
                __half2 b = __floats2half2_rn(di * acc.z, di * acc.w);
                *(uint2*)&As[r * LDA + lane * 4] = make_uint2(*(unsigned*)&a, *(unsigned*)&b);
            }
        } else {
            if constexpr (K == 32) As[r * LDA + lane] = __half(0.f);
            else *(uint2*)&As[r * LDA + lane * 4] = make_uint2(0u, 0u);
        }
    }
    __syncthreads();

    const int wm = wid % WM, wn = wid / WM;
    const int mrow = wm * MFRAG * 16;
    const int ncol = wn * NFRAG * 16;

    wmma::fragment<wmma::accumulator, 16, 16, 16, float> acc[MFRAG][NFRAG];
#pragma unroll
    for (int m = 0; m < MFRAG; m++)
#pragma unroll
        for (int n = 0; n < NFRAG; n++) wmma::fill_fragment(acc[m][n], 0.f);

#pragma unroll
    for (int k = 0; k < K; k += 16) {
        wmma::fragment<wmma::matrix_a, 16, 16, 16, __half, wmma::row_major> af[MFRAG];
#pragma unroll
        for (int m = 0; m < MFRAG; m++)
            wmma::load_matrix_sync(af[m], As + (mrow + m * 16) * LDA + k, LDA);
        wmma::fragment<wmma::matrix_b, 16, 16, 16, __half, wmma::row_major> bf[NFRAG];
#pragma unroll
        for (int n = 0; n < NFRAG; n++)
            wmma::load_matrix_sync(bf[n], Bs + k * LDB + ncol + n * 16, LDB);
#pragma unroll
        for (int m = 0; m < MFRAG; m++)
#pragma unroll
            for (int n = 0; n < NFRAG; n++)
                wmma::mma_sync(acc[m][n], af[m], bf[n], acc[m][n]);
    }
    __syncthreads();

    float* stage = (float*)smh + wid * 272;
    const int r = lane >> 1, c0 = (lane & 1) * 8;
#pragma unroll
    for (int m = 0; m < MFRAG; m++)
#pragma unroll
        for (int n = 0; n < NFRAG; n++) {
            wmma::store_matrix_sync(stage, acc[m][n], 16, wmma::mem_row_major);
            __syncwarp();
            int grow = row0 + mrow + m * 16 + r;
            int gcol = ncol + n * 16 + c0;
            float ds = 1.f;
            if constexpr (SCALE) ds = (grow < N_NODES) ? g_dis[grow] : 0.f;
            __half h[8];
#pragma unroll
            for (int j = 0; j < 8; j++) {
                float v = fmaxf(stage[r * 16 + c0 + j] + Bias[gcol + j], 0.f);
                if constexpr (SCALE) v *= ds;
                h[j] = __float2half(v);
            }
            *(uint4*)&Y[(size_t)grow * NOUT + gcol] = *(uint4*)h;
            __syncwarp();
        }
}

// ---------------- standalone tensor-core GEMM (layer 3: 128 -> 32, +dis scale) ----------------
template <int K, int NOUT, bool EPI, bool SCALE>
__global__ __launch_bounds__(256) void wgemm(
    const __half* __restrict__ A, const float* __restrict__ Wf,
    const float* __restrict__ Bias, __half* __restrict__ Y)
{
    constexpr int WN = (NOUT == 128) ? 2 : 1;
    constexpr int WM = 8 / WN;
    constexpr int NFRAG = NOUT / (WN * 16);
    constexpr int MFRAG = 2;
    constexpr int MBLK = WM * MFRAG * 16;
    constexpr int LDA = K + 8;
    constexpr int LDB = NOUT + 8;
    extern __shared__ __half smh[];
    __half* As = smh;
    __half* Bs = smh + MBLK * LDA;
    const int tid = threadIdx.x;
    const int row0 = blockIdx.x * MBLK;

    for (int i = tid; i < K * NOUT; i += 256) {
        int k = i / NOUT, n = i % NOUT;
        Bs[k * LDB + n] = __float2half(Wf[i]);
    }
    constexpr int CH = K / 8;
    for (int i = tid; i < MBLK * CH; i += 256) {
        int r = i / CH, ch = i % CH;
        uint4 v = *(const uint4*)&A[((size_t)(row0 + r)) * K + ch * 8];
        *(uint4*)&As[r * LDA + ch * 8] = v;
    }
    __syncthreads();

    const int wid = tid >> 5;
    const int wm = wid % WM, wn = wid / WM;
    const int mrow = wm * MFRAG * 16;
    const int ncol = wn * NFRAG * 16;

    wmma::fragment<wmma::accumulator, 16, 16, 16, float> acc[MFRAG][NFRAG];
#pragma unroll
    for (int m = 0; m < MFRAG; m++)
#pragma unroll
        for (int n = 0; n < NFRAG; n++) wmma::fill_fragment(acc[m][n], 0.f);

#pragma unroll
    for (int k = 0; k < K; k += 16) {
        wmma::fragment<wmma::matrix_a, 16, 16, 16, __half, wmma::row_major> af[MFRAG];
#pragma unroll
        for (int m = 0; m < MFRAG; m++)
            wmma::load_matrix_sync(af[m], As + (mrow + m * 16) * LDA + k, LDA);
        wmma::fragment<wmma::matrix_b, 16, 16, 16, __half, wmma::row_major> bf[NFRAG];
#pragma unroll
        for (int n = 0; n < NFRAG; n++)
            wmma::load_matrix_sync(bf[n], Bs + k * LDB + ncol + n * 16, LDB);
#pragma unroll
        for (int m = 0; m < MFRAG; m++)
#pragma unroll
            for (int n = 0; n < NFRAG; n++)
                wmma::mma_sync(acc[m][n], af[m], bf[n], acc[m][n]);
    }
    __syncthreads();

    float* stage = (float*)smh + wid * 272;
    const int lane = tid & 31;
    const int r = lane >> 1, c0 = (lane & 1) * 8;
#pragma unroll
    for (int m = 0; m < MFRAG; m++)
#pragma unroll
        for (int n = 0; n < NFRAG; n++) {
            wmma::store_matrix_sync(stage, acc[m][n], 16, wmma::mem_row_major);
            __syncwarp();
            int grow = row0 + mrow + m * 16 + r;
            int gcol = ncol + n * 16 + c0;
            float ds = 1.f;
            if constexpr (SCALE) ds = (grow < N_NODES) ? g_dis[grow] : 0.f;
            __half h[8];
#pragma unroll
            for (int j = 0; j < 8; j++) {
                float v = stage[r * 16 + c0 + j];
                if constexpr (EPI) v = fmaxf(v + Bias[gcol + j], 0.f);
                if constexpr (SCALE) v *= ds;
                h[j] = __float2half(v);
            }
            *(uint4*)&Y[(size_t)grow * NOUT + gcol] = *(uint4*)h;
            __syncwarp();
        }
}

// ---------------- final agg F=32 on pre-scaled G: out = relu(dis_i*(sum G)+b) ----------------
__global__ __launch_bounds__(256) void agg32_final(
    const __half* __restrict__ G, const float* __restrict__ B,
    float* __restrict__ outf, int N)
{
    int gw = (blockIdx.x * 256 + threadIdx.x) >> 5;
    int lane = threadIdx.x & 31;
    if (gw >= N) return;
    const float di = g_dis[gw];
    const int beg = g_rowptr[gw], end = g_rowptr[gw + 1];

    float acc = __half2float(G[(size_t)gw * 32 + lane]);
    int e = beg;
    for (; e + 8 <= end; e += 8) {
        int s[8];
#pragma unroll
        for (int j = 0; j < 8; j++) s[j] = g_colsrc[e + j];
        float v[8];
#pragma unroll
        for (int j = 0; j < 8; j++) v[j] = __half2float(G[(size_t)s[j] * 32 + lane]);
#pragma unroll
        for (int j = 0; j < 8; j++) acc += v[j];
    }
    for (; e < end; e++)
        acc += __half2float(G[(size_t)g_colsrc[e] * 32 + lane]);
    acc = fmaxf(acc * di + B[lane], 0.f);
    outf[(size_t)gw * 32 + lane] = acc;
}

extern "C" void kernel_launch(void* const* d_in, const int* in_sizes, int n_in,
                              void* d_out, int out_size) {
    const float* x  = (const float*)d_in[0];
    const void*  ed = d_in[1];
    const float* W1 = (const float*)d_in[2];
    const float* b1 = (const float*)d_in[3];
    const float* W2 = (const float*)d_in[4];
    const float* b2 = (const float*)d_in[5];
    const float* W3 = (const float*)d_in[6];
    const float* b3 = (const float*)d_in[7];
    float* out = (float*)d_out;

    const int N = in_sizes[0] / 32;
    const int E = in_sizes[1] / 2;
    const int nb = (N + 1023) / 1024;

    __half *xh, *h16, *hA, *s3h;
    cudaGetSymbolAddress((void**)&xh,  g_xh);
    cudaGetSymbolAddress((void**)&h16, g_h16);
    cudaGetSymbolAddress((void**)&hA,  g_hA);
    cudaGetSymbolAddress((void**)&s3h, g_s3h);

    const int ablk = (N * 32 + 255) / 256;
    const int fwork = (N * 8 > E) ? N * 8 : E;
    const int fblk = (fwork + 255) / 256;
    const int gblk = (N + 127) / 128;

    const int sm1 = (128 * 40 + 32 * 136) * 2;    // fused K=32
    const int sm2 = (128 * 136 + 128 * 136) * 2;  // fused K=128
    const int sm3 = (256 * 136 + 128 * 40) * 2;   // wgemm 128->32
    cudaFuncSetAttribute(fused_agg_wgemm<32, true>,   cudaFuncAttributeMaxDynamicSharedMemorySize, sm1);
    cudaFuncSetAttribute(fused_agg_wgemm<128, false>, cudaFuncAttributeMaxDynamicSharedMemorySize, sm2);
    cudaFuncSetAttribute(wgemm<128, 32, false, true>, cudaFuncAttributeMaxDynamicSharedMemorySize, sm3);

    // CSR + norm build (4 launches); x-convert fused into fill_csr
    prep_count<<<(E / 2 + 256) / 256, 256>>>(ed, N, E);
    scan_reduce<<<nb, 1024>>>(N);
    scan_write<<<nb, 1024>>>(N, nb);
    fill_csr<<<fblk, 256>>>(ed, x, E, N);

    // L1 fused: h16 = dis * relu(Agg(xh) @ W1 + b1)
    fused_agg_wgemm<32, true><<<gblk, 256, sm1>>>(xh, W1, b1, h16, N);

    // L2 fused: hA = relu(Agg(h16) @ W2 + b2)
    fused_agg_wgemm<128, false><<<gblk, 256, sm2>>>(h16, W2, b2, hA, N);

    // L3: s3h = dis * (hA @ W3); out = relu(dis*(sum s3h) + b3)
    wgemm<128, 32, false, true><<<(N + 255) / 256, 256, sm3>>>(hA, W3, nullptr, s3h);
    agg32_final<<<ablk, 256>>>(s3h, b3, out, N);
}

// round 17
// speedup vs baseline: 1.3703x; 1.3703x over previous
#include <cuda_runtime.h>
#include <cuda_fp16.h>
#include <mma.h>
#include <cstdint>
using namespace nvcuda;

#define N_NODES 100000
#define N_EDGES 1600000
#define NPAD    100352   // multiple of 256

__device__ int   g_cnt[N_NODES];     // zero at module load; re-zeroed in scan_write each run
__device__ int   g_fill[N_NODES];
__device__ float g_dis[N_NODES];
__device__ int   g_rowptr[N_NODES + 1];
__device__ int   g_bsum[256];
__device__ int   g_colsrc[N_EDGES];
__device__ __align__(16) __half g_xh  [(size_t)NPAD * 32];   // dis*x (pre-scaled)
__device__ __align__(16) __half g_s32h[(size_t)NPAD * 32];   // Agg(dis*x)*dis
__device__ __align__(16) __half g_h16 [(size_t)NPAD * 128];  // dis*h1 (pre-scaled)
__device__ __align__(16) __half g_hB  [(size_t)NPAD * 128];  // Agg of h16
__device__ __align__(16) __half g_hA  [(size_t)NPAD * 128];  // h2
__device__ __align__(16) __half g_s3h [(size_t)NPAD * 32];   // dis*(h2@W3) (pre-scaled)

// Per-block edge-dtype detection: sample high words of the first 64 int64 slots.
#define DETECT_IS64(w32, is64_var)                                   \
    __shared__ int s_any;                                            \
    if (threadIdx.x == 0) s_any = 0;                                 \
    __syncthreads();                                                 \
    if (threadIdx.x < 64 && (w32)[2 * threadIdx.x + 1] != 0)         \
        atomicOr(&s_any, 1);                                         \
    __syncthreads();                                                 \
    const bool is64_var = (s_any == 0);

__device__ __forceinline__ int edge_at(const void* ed, bool is64, size_t idx) {
    return is64 ? (int)((const long long*)ed)[idx] : ((const int*)ed)[idx];
}

// ---- count in-degrees (2 edges per thread) ----
__global__ void prep_count(const void* __restrict__ ed, int N, int E) {
    DETECT_IS64((const int*)ed, is64);
    int i = blockIdx.x * blockDim.x + threadIdx.x;
    int halfE = E >> 1;
    if (i < halfE) {
        int d0, d1;
        if (is64) {
            longlong2 v = ((const longlong2*)ed)[(size_t)halfE + i];
            d0 = (int)v.x; d1 = (int)v.y;
        } else {
            int2 v = ((const int2*)ed)[(size_t)halfE + i];
            d0 = v.x; d1 = v.y;
        }
        if ((unsigned)d0 < (unsigned)N) atomicAdd(&g_cnt[d0], 1);
        if ((unsigned)d1 < (unsigned)N) atomicAdd(&g_cnt[d1], 1);
    }
    if ((E & 1) && i == halfE) {
        int d = edge_at(ed, is64, (size_t)E + (E - 1));
        if ((unsigned)d < (unsigned)N) atomicAdd(&g_cnt[d], 1);
    }
}

// ---- scan pass 1: per-block sums (warp shuffles) + dis/fill init ----
__global__ __launch_bounds__(1024) void scan_reduce(int N) {
    __shared__ int ws[32];
    int idx = blockIdx.x * 1024 + threadIdx.x;
    int c = (idx < N) ? g_cnt[idx] : 0;
    if (idx < N) { g_dis[idx] = rsqrtf((float)(c + 1)); g_fill[idx] = 0; }
    int v = c;
#pragma unroll
    for (int o = 16; o; o >>= 1) v += __shfl_down_sync(0xffffffffu, v, o);
    if ((threadIdx.x & 31) == 0) ws[threadIdx.x >> 5] = v;
    __syncthreads();
    if (threadIdx.x < 32) {
        int t = ws[threadIdx.x];
#pragma unroll
        for (int o = 16; o; o >>= 1) t += __shfl_down_sync(0xffffffffu, t, o);
        if (threadIdx.x == 0) g_bsum[blockIdx.x] = t;
    }
}

// ---- scan pass 2: shuffle scans, exclusive rowptr; re-zero cnt ----
__global__ __launch_bounds__(1024) void scan_write(int N, int nb) {
    __shared__ int ws[32];
    __shared__ int tops;
    const int tid = threadIdx.x;
    const int lane = tid & 31;
    const int idx = blockIdx.x * 1024 + tid;
    int v = (idx < N) ? g_cnt[idx] : 0;
    int inc = v;
#pragma unroll
    for (int o = 1; o < 32; o <<= 1) {
        int t = __shfl_up_sync(0xffffffffu, inc, o);
        if (lane >= o) inc += t;
    }
    if (lane == 31) ws[tid >> 5] = inc;
    __syncthreads();
    if (tid < 32) {                     // warp 0: exclusive scan of 32 warp totals
        int t = ws[tid];
        int ti = t;
#pragma unroll
        for (int o = 1; o < 32; o <<= 1) {
            int u = __shfl_up_sync(0xffffffffu, ti, o);
            if (tid >= o) ti += u;
        }
        ws[tid] = ti - t;
    } else if (tid < 64) {              // warp 1: top-level scan of nb (<=128) block sums
        int l = tid - 32;
        int b[4];
#pragma unroll
        for (int k = 0; k < 4; k++) { int j = l * 4 + k; b[k] = (j < nb) ? g_bsum[j] : 0; }
        int tot = b[0] + b[1] + b[2] + b[3];
        int ti = tot;
#pragma unroll
        for (int o = 1; o < 32; o <<= 1) {
            int u = __shfl_up_sync(0xffffffffu, ti, o);
            if (l >= o) ti += u;
        }
        int ex = ti - tot;
#pragma unroll
        for (int k = 0; k < 4; k++) {
            int j = l * 4 + k;
            if (j == (int)blockIdx.x) tops = ex;
            ex += b[k];
        }
        if (blockIdx.x == (unsigned)(nb - 1)) {
            int total = __shfl_sync(0xffffffffu, ti, 31);
            if (l == 0) g_rowptr[N] = total;
        }
    }
    __syncthreads();
    if (idx < N) {
        g_rowptr[idx] = tops + ws[tid >> 5] + (inc - v);   // global exclusive
        g_cnt[idx] = 0;                                    // ready for next replay
    }
}

// ---- fill CSR + fused scaled x->fp16 convert (dis ready after scan_write) ----
__global__ void fill_csr(const void* __restrict__ ed, const float* __restrict__ x,
                         int E, int N) {
    DETECT_IS64((const int*)ed, is64);
    int i = blockIdx.x * blockDim.x + threadIdx.x;
    if (i < N * 8) {                      // 4 floats per thread, scaled by dis[row]
        float4 f = ((const float4*)x)[i];
        float d = g_dis[i >> 3];
        __half2 a = __floats2half2_rn(d * f.x, d * f.y);
        __half2 b = __floats2half2_rn(d * f.z, d * f.w);
        ((uint2*)g_xh)[i] = make_uint2(*(unsigned*)&a, *(unsigned*)&b);
    }
    if (i < E) {
        int s = edge_at(ed, is64, i);
        int d = edge_at(ed, is64, (size_t)E + i);
        if ((unsigned)s < (unsigned)N && (unsigned)d < (unsigned)N) {
            int pos = g_rowptr[d] + atomicAdd(&g_fill[d], 1);
            g_colsrc[pos] = s;
        }
    }
}

// ---------------- tensor-core GEMM: Y[N,NOUT] = A[N,K](fp16) @ W(fp32->fp16) ----
// EPI: +bias, relu.  SCALE: multiply output row by g_dis[row] (pre-scaling for agg).
template <int K, int NOUT, bool EPI, bool SCALE>
__global__ __launch_bounds__(256) void wgemm(
    const __half* __restrict__ A, const float* __restrict__ Wf,
    const float* __restrict__ Bias, __half* __restrict__ Y)
{
    constexpr int WN = (NOUT == 128) ? 2 : 1;
    constexpr int WM = 8 / WN;
    constexpr int NFRAG = NOUT / (WN * 16);
    constexpr int MFRAG = 2;
    constexpr int MBLK = WM * MFRAG * 16;
    constexpr int LDA = K + 8;
    constexpr int LDB = NOUT + 8;
    extern __shared__ __half smh[];
    __half* As = smh;
    __half* Bs = smh + MBLK * LDA;
    const int tid = threadIdx.x;
    const int row0 = blockIdx.x * MBLK;

    for (int i = tid; i < K * NOUT; i += 256) {
        int k = i / NOUT, n = i % NOUT;
        Bs[k * LDB + n] = __float2half(Wf[i]);
    }
    constexpr int CH = K / 8;
    for (int i = tid; i < MBLK * CH; i += 256) {
        int r = i / CH, ch = i % CH;
        uint4 v = *(const uint4*)&A[((size_t)(row0 + r)) * K + ch * 8];
        *(uint4*)&As[r * LDA + ch * 8] = v;
    }
    __syncthreads();

    const int wid = tid >> 5;
    const int wm = wid % WM, wn = wid / WM;
    const int mrow = wm * MFRAG * 16;
    const int ncol = wn * NFRAG * 16;

    wmma::fragment<wmma::accumulator, 16, 16, 16, float> acc[MFRAG][NFRAG];
#pragma unroll
    for (int m = 0; m < MFRAG; m++)
#pragma unroll
        for (int n = 0; n < NFRAG; n++) wmma::fill_fragment(acc[m][n], 0.f);

#pragma unroll
    for (int k = 0; k < K; k += 16) {
        wmma::fragment<wmma::matrix_a, 16, 16, 16, __half, wmma::row_major> af[MFRAG];
#pragma unroll
        for (int m = 0; m < MFRAG; m++)
            wmma::load_matrix_sync(af[m], As + (mrow + m * 16) * LDA + k, LDA);
        wmma::fragment<wmma::matrix_b, 16, 16, 16, __half, wmma::row_major> bf[NFRAG];
#pragma unroll
        for (int n = 0; n < NFRAG; n++)
            wmma::load_matrix_sync(bf[n], Bs + k * LDB + ncol + n * 16, LDB);
#pragma unroll
        for (int m = 0; m < MFRAG; m++)
#pragma unroll
            for (int n = 0; n < NFRAG; n++)
                wmma::mma_sync(acc[m][n], af[m], bf[n], acc[m][n]);
    }
    __syncthreads();

    float* stage = (float*)smh + wid * 272;
    const int lane = tid & 31;
    const int r = lane >> 1, c0 = (lane & 1) * 8;
#pragma unroll
    for (int m = 0; m < MFRAG; m++)
#pragma unroll
        for (int n = 0; n < NFRAG; n++) {
            wmma::store_matrix_sync(stage, acc[m][n], 16, wmma::mem_row_major);
            __syncwarp();
            int grow = row0 + mrow + m * 16 + r;
            int gcol = ncol + n * 16 + c0;
            float ds = 1.f;
            if constexpr (SCALE) ds = (grow < N_NODES) ? g_dis[grow] : 0.f;
            __half h[8];
#pragma unroll
            for (int j = 0; j < 8; j++) {
                float v = stage[r * 16 + c0 + j];
                if constexpr (EPI) v = fmaxf(v + Bias[gcol + j], 0.f);
                if constexpr (SCALE) v *= ds;
                h[j] = __float2half(v);
            }
            *(uint4*)&Y[(size_t)grow * NOUT + gcol] = *(uint4*)h;
            __syncwarp();
        }
}

// ---------------- agg F=32 on pre-scaled G: out = dis_i * (Σ G[s] + G[i]) ----------------
template <bool EPI, bool OUTF>
__global__ __launch_bounds__(256) void agg32_kernel(
    const __half* __restrict__ G, const float* __restrict__ B,
    __half* __restrict__ outh, float* __restrict__ outf, int N)
{
    int gw = (blockIdx.x * 256 + threadIdx.x) >> 5;
    int lane = threadIdx.x & 31;
    if (gw >= N) return;
    const float di = g_dis[gw];
    const int beg = g_rowptr[gw], end = g_rowptr[gw + 1];

    float acc = __half2float(G[(size_t)gw * 32 + lane]);
    int e = beg;
    for (; e + 8 <= end; e += 8) {
        int s[8];
#pragma unroll
        for (int j = 0; j < 8; j++) s[j] = g_colsrc[e + j];
        float v[8];
#pragma unroll
        for (int j = 0; j < 8; j++) v[j] = __half2float(G[(size_t)s[j] * 32 + lane]);
#pragma unroll
        for (int j = 0; j < 8; j++) acc += v[j];
    }
    for (; e < end; e++)
        acc += __half2float(G[(size_t)g_colsrc[e] * 32 + lane]);
    acc *= di;
    if constexpr (EPI) acc = fmaxf(acc + B[lane], 0.f);
    if constexpr (OUTF) outf[(size_t)gw * 32 + lane] = acc;
    else               outh[(size_t)gw * 32 + lane] = __float2half(acc);
}

// ---------------- agg F=128 on pre-scaled G ----------------
__device__ __forceinline__ float4 h4_to_f4(uint2 v) {
    __half2 a = *(__half2*)&v.x, b = *(__half2*)&v.y;
    float2 fa = __half22float2(a), fb = __half22float2(b);
    return make_float4(fa.x, fa.y, fb.x, fb.y);
}

__global__ __launch_bounds__(256) void agg128h_kernel(
    const __half* __restrict__ G, __half* __restrict__ out, int N)
{
    int gw = (blockIdx.x * 256 + threadIdx.x) >> 5;
    int lane = threadIdx.x & 31;
    if (gw >= N) return;
    const float di = g_dis[gw];
    const int beg = g_rowptr[gw], end = g_rowptr[gw + 1];

    float4 acc = h4_to_f4(((const uint2*)(G + (size_t)gw * 128))[lane]);
    int e = beg;
    for (; e + 8 <= end; e += 8) {
        int s[8];
#pragma unroll
        for (int j = 0; j < 8; j++) s[j] = g_colsrc[e + j];
        uint2 raw[8];
#pragma unroll
        for (int j = 0; j < 8; j++) raw[j] = ((const uint2*)(G + (size_t)s[j] * 128))[lane];
#pragma unroll
        for (int j = 0; j < 8; j++) {
            float4 v = h4_to_f4(raw[j]);
            acc.x += v.x; acc.y += v.y; acc.z += v.z; acc.w += v.w;
        }
    }
    for (; e < end; e++) {
        float4 v = h4_to_f4(((const uint2*)(G + (size_t)g_colsrc[e] * 128))[lane]);
        acc.x += v.x; acc.y += v.y; acc.z += v.z; acc.w += v.w;
    }
    __half2 o01 = __floats2half2_rn(di * acc.x, di * acc.y);
    __half2 o23 = __floats2half2_rn(di * acc.z, di * acc.w);
    uint2 pk = make_uint2(*(unsigned*)&o01, *(unsigned*)&o23);
    ((uint2*)(out + (size_t)gw * 128))[lane] = pk;
}

extern "C" void kernel_launch(void* const* d_in, const int* in_sizes, int n_in,
                              void* d_out, int out_size) {
    const float* x  = (const float*)d_in[0];
    const void*  ed = d_in[1];
    const float* W1 = (const float*)d_in[2];
    const float* b1 = (const float*)d_in[3];
    const float* W2 = (const float*)d_in[4];
    const float* b2 = (const float*)d_in[5];
    const float* W3 = (const float*)d_in[6];
    const float* b3 = (const float*)d_in[7];
    float* out = (float*)d_out;

    const int N = in_sizes[0] / 32;
    const int E = in_sizes[1] / 2;
    const int nb = (N + 1023) / 1024;

    __half *xh, *s32h, *h16, *hB, *hA, *s3h;
    cudaGetSymbolAddress((void**)&xh,   g_xh);
    cudaGetSymbolAddress((void**)&s32h, g_s32h);
    cudaGetSymbolAddress((void**)&h16,  g_h16);
    cudaGetSymbolAddress((void**)&hB,   g_hB);
    cudaGetSymbolAddress((void**)&hA,   g_hA);
    cudaGetSymbolAddress((void**)&s3h,  g_s3h);

    const int ablk = (N * 32 + 255) / 256;
    const int fwork = (N * 8 > E) ? N * 8 : E;
    const int fblk = (fwork + 255) / 256;

    const int sm1 = (128 * 40 + 32 * 136) * 2;
    const int sm2 = (128 * 136 + 128 * 136) * 2;
    const int sm3 = (256 * 136 + 128 * 40) * 2;
    cudaFuncSetAttribute(wgemm<32, 128, true, true>,   cudaFuncAttributeMaxDynamicSharedMemorySize, sm1);
    cudaFuncSetAttribute(wgemm<128, 128, true, false>, cudaFuncAttributeMaxDynamicSharedMemorySize, sm2);
    cudaFuncSetAttribute(wgemm<128, 32, false, true>,  cudaFuncAttributeMaxDynamicSharedMemorySize, sm3);

    // CSR + norm build (4 launches); x-convert fused into fill_csr
    prep_count<<<(E / 2 + 256) / 256, 256>>>(ed, N, E);
    scan_reduce<<<nb, 1024>>>(N);
    scan_write<<<nb, 1024>>>(N, nb);
    fill_csr<<<fblk, 256>>>(ed, x, E, N);

    // L1: relu(Agg(x) @ W1 + b1); wgemm writes dis*h1 (pre-scaled for next agg)
    agg32_kernel<false, false><<<ablk, 256>>>(xh, nullptr, s32h, nullptr, N);
    wgemm<32, 128, true, true><<<(N + 127) / 128, 256, sm1>>>(s32h, W1, b1, h16);

    // L2: relu(Agg(h1) @ W2 + b2)
    agg128h_kernel<<<ablk, 256>>>(h16, hB, N);
    wgemm<128, 128, true, false><<<(N + 127) / 128, 256, sm2>>>(hB, W2, b2, hA);

    // L3: relu(Agg(h2 @ W3) + b3); wgemm3 writes dis*(h2@W3)
    wgemm<128, 32, false, true><<<(N + 255) / 256, 256, sm3>>>(hA, W3, nullptr, s3h);
    agg32_kernel<true, true><<<ablk, 256>>>(s3h, b3, nullptr, out, N);
}